// round 7
// baseline (speedup 1.0000x reference)
#include <cuda_runtime.h>
#include <cuda_bf16.h>
#include <math.h>
#include <stdint.h>

// ---------------------------------------------------------------------------
// MultiScaleDeformableAttention, fp32 in/out.
// GEMMs: mma.sync bf16 m16n8k16, 3-term compensation with register reuse
//   (A'=[Ah|Al] K=512; acc += Ah*Bh + Ah*Bl + Al*Bh).
// Round-7: sampler Phase B re-mapped to warp=head, lane=channel (LDG.32,
// one 128B line per instruction -> 1.0 cyc/wavefront instead of 2.07).
// ---------------------------------------------------------------------------

#define NQ    20197
#define BSZ   2
#define EDIM  256
#define NLVL  4
#define MTOT  (BSZ * NQ)     // 40394

#define KP2   512            // [hi(256) | lo(256)] row stride
#define BK    32
#define NKIT  8              // 256 / BK
#define APAD2 72             // stage row elems (64 data + 8 pad)
#define TILE_E (128 * APAD2)
#define STAGE_B (2 * TILE_E * 2)     // 36864 B per stage (A + B)
#define SMEM_GEMM (3 * STAGE_B)      // 110592 B

#define QASTR 384            // fused SO|AW output row stride

// ------------------------------- scratch ------------------------------------
__device__ float g_V  [MTOT * EDIM];
__device__ float g_QA [(size_t)MTOT * QASTR];   // [SO(256) | AWL(128)]
__device__ __nv_bfloat16 g_Aval[(size_t)MTOT * KP2];
__device__ __nv_bfloat16 g_Aq  [(size_t)MTOT * KP2];
__device__ __nv_bfloat16 g_Atmp[(size_t)MTOT * KP2];
__device__ __nv_bfloat16 g_Bv [256 * KP2];
__device__ __nv_bfloat16 g_Bqa[QASTR * KP2];
__device__ __nv_bfloat16 g_Bo [256 * KP2];
__device__ float g_biasQA[QASTR];

// -------------------------- small PTX helpers -------------------------------
__device__ __forceinline__ uint32_t smem_u32(const void* p) {
    uint32_t a;
    asm("{ .reg .u64 t; cvta.to.shared.u64 t, %1; cvt.u32.u64 %0, t; }"
        : "=r"(a) : "l"(p));
    return a;
}
__device__ __forceinline__ void cp_async16(uint32_t dst, const void* src) {
    asm volatile("cp.async.cg.shared.global [%0], [%1], 16;"
                 :: "r"(dst), "l"(src) : "memory");
}
__device__ __forceinline__ void cp_commit() {
    asm volatile("cp.async.commit_group;" ::: "memory");
}
template <int N>
__device__ __forceinline__ void cp_wait() {
    asm volatile("cp.async.wait_group %0;" :: "n"(N) : "memory");
}
__device__ __forceinline__ void ldmatrix_x4(uint32_t* r, uint32_t addr) {
    asm volatile("ldmatrix.sync.aligned.m8n8.x4.shared.b16 {%0,%1,%2,%3}, [%4];"
                 : "=r"(r[0]), "=r"(r[1]), "=r"(r[2]), "=r"(r[3]) : "r"(addr));
}
__device__ __forceinline__ void mma_bf16(float* c, const uint32_t* a,
                                         uint32_t b0, uint32_t b1) {
    asm volatile(
        "mma.sync.aligned.m16n8k16.row.col.f32.bf16.bf16.f32 "
        "{%0,%1,%2,%3}, {%4,%5,%6,%7}, {%8,%9}, {%0,%1,%2,%3};"
        : "+f"(c[0]), "+f"(c[1]), "+f"(c[2]), "+f"(c[3])
        : "r"(a[0]), "r"(a[1]), "r"(a[2]), "r"(a[3]), "r"(b0), "r"(b1));
}

// ---------------------------------------------------------------------------
// fp32 activation -> bf16 [hi(256) | lo(256)], row stride KP2
// ---------------------------------------------------------------------------
__global__ __launch_bounds__(256) void split_cat(
    const float* __restrict__ x, __nv_bfloat16* __restrict__ out, int n4)
{
    const int i = blockIdx.x * 256 + threadIdx.x;
    if (i >= n4) return;
    const float4 v = ((const float4*)x)[i];
    const int row = i >> 6;
    const int c4  = (i & 63) << 2;
    __nv_bfloat16 h[4], l[4];
    const float f[4] = {v.x, v.y, v.z, v.w};
#pragma unroll
    for (int k = 0; k < 4; k++) {
        h[k] = __float2bfloat16(f[k]);
        l[k] = __float2bfloat16(f[k] - __bfloat162float(h[k]));
    }
    __nv_bfloat16* base = out + (size_t)row * KP2 + c4;
    *(uint2*)(base)       = *(const uint2*)h;
    *(uint2*)(base + 256) = *(const uint2*)l;
}

// ---------------------------------------------------------------------------
// One-shot weight prep: W[K=256,N] -> B't[N][KP2]=[h|l] transposed + bias cat.
// ---------------------------------------------------------------------------
__global__ __launch_bounds__(256) void prep_weights(
    const float* __restrict__ Wv,  const float* __restrict__ Wso,
    const float* __restrict__ Waw, const float* __restrict__ Wo,
    const float* __restrict__ bso, const float* __restrict__ baw)
{
    const int idx = blockIdx.x * 256 + threadIdx.x;
    const float* W;
    __nv_bfloat16* Bt;
    int li, N, nofs = 0;
    if (idx < 65536)        { W = Wv;  Bt = g_Bv;  li = idx;          N = 256; }
    else if (idx < 131072)  { W = Wso; Bt = g_Bqa; li = idx - 65536;  N = 256; }
    else if (idx < 163840)  { W = Waw; Bt = g_Bqa; li = idx - 131072; N = 128; nofs = 256; }
    else if (idx < 229376)  { W = Wo;  Bt = g_Bo;  li = idx - 163840; N = 256; }
    else {
        const int i = idx - 229376;
        if (i < 256)      g_biasQA[i] = bso[i];
        else if (i < 384) g_biasQA[i] = baw[i - 256];
        return;
    }
    const int k = li / N, n = li % N;
    const float v = W[li];
    const __nv_bfloat16 h = __float2bfloat16(v);
    const __nv_bfloat16 l = __float2bfloat16(v - __bfloat162float(h));
    __nv_bfloat16* base = Bt + (size_t)(n + nofs) * KP2 + k;
    base[0]   = h;
    base[256] = l;
}

// ---------------------------------------------------------------------------
// bf16 mma GEMM with register-reuse 3-term compensation (round-6, unchanged).
// ---------------------------------------------------------------------------
__global__ __launch_bounds__(256, 2) void gemm_mma(
    const __nv_bfloat16* __restrict__ A, const __nv_bfloat16* __restrict__ Bt,
    const float* __restrict__ bias, const float* __restrict__ res,
    float* __restrict__ C, int M, int N)
{
    extern __shared__ __align__(16) char smem[];
    const uint32_t sBase = smem_u32(smem);

    const int tid  = threadIdx.x;
    const int lane = tid & 31;
    const int wid  = tid >> 5;
    const int wm   = wid & 3;
    const int wn   = wid >> 2;
    const int m0   = blockIdx.x * 128;
    const int n0   = blockIdx.y * 128;

    auto load_stage = [&](int stg, int kt) {
        const int kbase = kt * BK;
        const uint32_t sA = sBase + (uint32_t)stg * STAGE_B;
        const uint32_t sB = sA + TILE_E * 2;
#pragma unroll
        for (int it = 0; it < 4; it++) {
            const int c   = tid + it * 256;
            const int row = c >> 3;
            const int seg = (c & 7) << 3;
            const int gcol = (seg < 32) ? (kbase + seg) : (256 + kbase + seg - 32);
            const uint32_t soff = (uint32_t)(row * APAD2 + seg) * 2;
            const int ar = min(m0 + row, M - 1);
            cp_async16(sA + soff, A + (size_t)ar * KP2 + gcol);
            cp_async16(sB + soff, Bt + (size_t)(n0 + row) * KP2 + gcol);
        }
    };

    float acc[2][8][4];
#pragma unroll
    for (int mi = 0; mi < 2; mi++)
#pragma unroll
        for (int nj = 0; nj < 8; nj++)
#pragma unroll
            for (int k = 0; k < 4; k++) acc[mi][nj][k] = 0.f;

    load_stage(0, 0); cp_commit();
    load_stage(1, 1); cp_commit();

    int stg = 0;
#pragma unroll 1
    for (int kt = 0; kt < NKIT; kt++) {
        cp_wait<1>();
        __syncthreads();

        if (kt + 2 < NKIT) load_stage((stg + 2) % 3, kt + 2);
        cp_commit();

        const uint32_t aB = sBase + (uint32_t)stg * STAGE_B;
        const uint32_t bB = aB + TILE_E * 2;

#pragma unroll
        for (int ks = 0; ks < 2; ks++) {
            uint32_t ah[2][4], al[2][4];
#pragma unroll
            for (int mi = 0; mi < 2; mi++) {
                const int row = wm * 32 + mi * 16 + (lane & 15);
                const int col = ks * 16 + ((lane >> 4) << 3);
                ldmatrix_x4(ah[mi], aB + (uint32_t)(row * APAD2 + col) * 2);
                ldmatrix_x4(al[mi], aB + (uint32_t)(row * APAD2 + 32 + col) * 2);
            }
#pragma unroll
            for (int njp = 0; njp < 4; njp++) {
                const int row = wn * 64 + njp * 16 + ((lane >> 4) & 1) * 8 + (lane & 7);
                const int col = ks * 16 + ((lane >> 3) & 1) * 8;
                uint32_t bh[4], bl[4];
                ldmatrix_x4(bh, bB + (uint32_t)(row * APAD2 + col) * 2);
                ldmatrix_x4(bl, bB + (uint32_t)(row * APAD2 + 32 + col) * 2);
#pragma unroll
                for (int mi = 0; mi < 2; mi++) {
                    float* a0 = acc[mi][njp * 2];
                    float* a1 = acc[mi][njp * 2 + 1];
                    mma_bf16(a0, ah[mi], bh[0], bh[1]);
                    mma_bf16(a1, ah[mi], bh[2], bh[3]);
                    mma_bf16(a0, ah[mi], bl[0], bl[1]);
                    mma_bf16(a1, ah[mi], bl[2], bl[3]);
                    mma_bf16(a0, al[mi], bh[0], bh[1]);
                    mma_bf16(a1, al[mi], bh[2], bh[3]);
                }
            }
        }
        stg = (stg + 1) % 3;
    }

#pragma unroll
    for (int mi = 0; mi < 2; mi++) {
#pragma unroll
        for (int nj = 0; nj < 8; nj++) {
            const int col = n0 + wn * 64 + nj * 8 + (lane & 3) * 2;
            const int r0  = m0 + wm * 32 + mi * 16 + (lane >> 2);
            const int r1  = r0 + 8;
            const float b0 = bias[col], b1 = bias[col + 1];
            if (r0 < M) {
                float2 o = make_float2(acc[mi][nj][0] + b0, acc[mi][nj][1] + b1);
                if (res) {
                    const float2 rv = *(const float2*)(res + (size_t)r0 * N + col);
                    o.x += rv.x; o.y += rv.y;
                }
                *(float2*)(C + (size_t)r0 * N + col) = o;
            }
            if (r1 < M) {
                float2 o = make_float2(acc[mi][nj][2] + b0, acc[mi][nj][3] + b1);
                if (res) {
                    const float2 rv = *(const float2*)(res + (size_t)r1 * N + col);
                    o.x += rv.x; o.y += rv.y;
                }
                *(float2*)(C + (size_t)r1 * N + col) = o;
            }
        }
    }
}

// ---------------------------------------------------------------------------
// Sampler v3: one block per query (256 threads = 8 warps = 8 heads).
// Phase A (threads 0..127, one per (h,pt)): softmax over 16 logits in
// 16-lane shuffle groups; store pre-scaled BYTE offsets (clamped) and
// aw-folded corner weights to smem.
// Phase B: warp = head, lane = channel. Per point: 2 broadcast LDS +
// 4 single-line LDG.32 + 8 FFMA. Every gather instruction touches exactly
// one 128B line -> 1.0 cyc/wavefront L1tex rate.
// ---------------------------------------------------------------------------
__global__ __launch_bounds__(256) void msda_sample_w(
    const float* __restrict__ V, const float* __restrict__ QA,
    const float* __restrict__ refp,
    const int* __restrict__ shapes, const int* __restrict__ starts,
    __nv_bfloat16* __restrict__ outCat)
{
    __shared__ int4   sOff[16][8];   // [pt][h]: 4 corner byte-offsets
    __shared__ float4 sW  [16][8];   // [pt][h]: 4 corner weights * aw

    const int tid = threadIdx.x;
    const int bq  = blockIdx.x;

    // -------------------- Phase A (warps 0..3 fully active) ----------------
    if (tid < 128) {
        const int h  = tid >> 4;
        const int pt = tid & 15;

        const float logit = QA[(size_t)bq * QASTR + 256 + h * 16 + pt];
        float mx = logit;
#pragma unroll
        for (int off = 8; off; off >>= 1)
            mx = fmaxf(mx, __shfl_xor_sync(0xffffffffu, mx, off, 16));
        const float e = expf(logit - mx);
        float sm = e;
#pragma unroll
        for (int off = 8; off; off >>= 1)
            sm += __shfl_xor_sync(0xffffffffu, sm, off, 16);
        const float aw = e / sm;

        const int l  = pt >> 2;
        const int H  = shapes[2 * l + 0];
        const int W  = shapes[2 * l + 1];
        const int st = starts[l];
        const float2 rp = *(const float2*)(refp + ((size_t)bq * NLVL + l) * 2);
        const float2 so = *(const float2*)(QA + (size_t)bq * QASTR + h * 32 + pt * 2);

        const float x = fmaf(rp.x, (float)W, so.x) - 0.5f;
        const float y = fmaf(rp.y, (float)H, so.y) - 0.5f;
        const float xf = floorf(x), yf = floorf(y);
        const int x0 = (int)xf, y0 = (int)yf;
        const float wx1 = x - xf, wx0 = 1.f - wx1;
        const float wy1 = y - yf, wy0 = 1.f - wy1;

        const bool vx0 = (x0 >= 0) && (x0 < W);
        const bool vx1 = (x0 + 1 >= 0) && (x0 + 1 < W);
        const bool vy0 = (y0 >= 0) && (y0 < H);
        const bool vy1 = (y0 + 1 >= 0) && (y0 + 1 < H);

        const int cx0 = max(0, min(x0,     W - 1));
        const int cx1 = max(0, min(x0 + 1, W - 1));
        const int cy0 = max(0, min(y0,     H - 1));
        const int cy1 = max(0, min(y0 + 1, H - 1));

        // byte offsets into V (row stride EDIM*4 = 1024B)
        int4 o;
        o.x = (st + cy0 * W + cx0) << 10;
        o.y = (st + cy0 * W + cx1) << 10;
        o.z = (st + cy1 * W + cx0) << 10;
        o.w = (st + cy1 * W + cx1) << 10;

        float4 w4;
        w4.x = (vx0 && vy0) ? wx0 * wy0 * aw : 0.f;
        w4.y = (vx1 && vy0) ? wx1 * wy0 * aw : 0.f;
        w4.z = (vx0 && vy1) ? wx0 * wy1 * aw : 0.f;
        w4.w = (vx1 && vy1) ? wx1 * wy1 * aw : 0.f;

        sOff[pt][h] = o;
        sW  [pt][h] = w4;
    }
    __syncthreads();

    // -------------------- Phase B: warp = head, lane = channel -------------
    const int h    = tid >> 5;
    const int lane = tid & 31;
    const int b    = bq / NQ;

    const char* vb = (const char*)(V + (size_t)b * NQ * EDIM + h * 32 + lane);

    float acc = 0.f;
#pragma unroll
    for (int pt = 0; pt < 16; pt++) {
        const int4   o = sOff[pt][h];
        const float4 w = sW [pt][h];
        const float v0 = *(const float*)(vb + o.x);
        const float v1 = *(const float*)(vb + o.y);
        const float v2 = *(const float*)(vb + o.z);
        const float v3 = *(const float*)(vb + o.w);
        acc = fmaf(w.x, v0, acc);
        acc = fmaf(w.y, v1, acc);
        acc = fmaf(w.z, v2, acc);
        acc = fmaf(w.w, v3, acc);
    }

    // emit [hi|lo] bf16 row for the output GEMM
    const __nv_bfloat16 hh = __float2bfloat16(acc);
    const __nv_bfloat16 ll = __float2bfloat16(acc - __bfloat162float(hh));
    __nv_bfloat16* base = outCat + (size_t)bq * KP2 + h * 32 + lane;
    base[0]   = hh;
    base[256] = ll;
}

// ---------------------------------------------------------------------------
// Launch
// ---------------------------------------------------------------------------
extern "C" void kernel_launch(void* const* d_in, const int* in_sizes, int n_in,
                              void* d_out, int out_size)
{
    const float* query  = (const float*)d_in[0];
    const float* value  = (const float*)d_in[1];
    const float* refp   = (const float*)d_in[2];
    const int*   shapes = (const int*)  d_in[3];
    const int*   starts = (const int*)  d_in[4];
    const float* Wv  = (const float*)d_in[5];
    const float* bv  = (const float*)d_in[6];
    const float* Wso = (const float*)d_in[7];
    const float* bso = (const float*)d_in[8];
    const float* Waw = (const float*)d_in[9];
    const float* baw = (const float*)d_in[10];
    const float* Wo  = (const float*)d_in[11];
    const float* bo  = (const float*)d_in[12];
    float* out = (float*)d_out;

    const int M = in_sizes[0] / EDIM;   // 40394

    float *pV, *pQA, *pBiasQA;
    __nv_bfloat16 *pAval, *pAq, *pAtmp, *pBv, *pBqa, *pBo;
    cudaGetSymbolAddress((void**)&pV,     g_V);
    cudaGetSymbolAddress((void**)&pQA,    g_QA);
    cudaGetSymbolAddress((void**)&pBiasQA,g_biasQA);
    cudaGetSymbolAddress((void**)&pAval,  g_Aval);
    cudaGetSymbolAddress((void**)&pAq,    g_Aq);
    cudaGetSymbolAddress((void**)&pAtmp,  g_Atmp);
    cudaGetSymbolAddress((void**)&pBv,    g_Bv);
    cudaGetSymbolAddress((void**)&pBqa,   g_Bqa);
    cudaGetSymbolAddress((void**)&pBo,    g_Bo);

    cudaFuncSetAttribute(gemm_mma, cudaFuncAttributeMaxDynamicSharedMemorySize, SMEM_GEMM);

    const int n4 = M * (EDIM / 4);
    const int cvtBlocks = (n4 + 255) / 256;
    const int mTiles = (M + 127) / 128;
    const dim3 g256(mTiles, 2);
    const dim3 g384(mTiles, 3);

    split_cat<<<cvtBlocks, 256>>>(value, pAval, n4);
    split_cat<<<cvtBlocks, 256>>>(query, pAq,   n4);
    prep_weights<<<(229760 + 255) / 256, 256>>>(Wv, Wso, Waw, Wo, bso, baw);

    gemm_mma<<<g256, 256, SMEM_GEMM>>>(pAval, pBv,  bv,      nullptr, pV,  M, 256);
    gemm_mma<<<g384, 256, SMEM_GEMM>>>(pAq,   pBqa, pBiasQA, nullptr, pQA, M, QASTR);
    msda_sample_w<<<M, 256>>>(pV, pQA, refp, shapes, starts, pAtmp);
    gemm_mma<<<g256, 256, SMEM_GEMM>>>(pAtmp, pBo,  bo,      query,   out, M, 256);
}

// round 8
// speedup vs baseline: 1.0566x; 1.0566x over previous
#include <cuda_runtime.h>
#include <cuda_bf16.h>
#include <math.h>
#include <stdint.h>

// ---------------------------------------------------------------------------
// MultiScaleDeformableAttention, fp32 in/out.
// GEMMs: mma.sync bf16 m16n8k16, 3-term compensation with register reuse
//   (A'=[Ah|Al] K=512; acc += Ah*Bh + Ah*Bl + Al*Bh).  [Round-6, unchanged]
// Round-8 sampler: block = 2 queries; warp = (query, head-pair);
//   16 lanes x float2 per head -> every LDG.64 touches exactly 2 lines
//   (one per half-warp) = min of max(issue, wavefront) cost.
// ---------------------------------------------------------------------------

#define NQ    20197
#define BSZ   2
#define EDIM  256
#define NLVL  4
#define MTOT  (BSZ * NQ)     // 40394

#define KP2   512            // [hi(256) | lo(256)] row stride
#define BK    32
#define NKIT  8              // 256 / BK
#define APAD2 72             // stage row elems (64 data + 8 pad)
#define TILE_E (128 * APAD2)
#define STAGE_B (2 * TILE_E * 2)     // 36864 B per stage (A + B)
#define SMEM_GEMM (3 * STAGE_B)      // 110592 B

#define QASTR 384            // fused SO|AW output row stride

// ------------------------------- scratch ------------------------------------
__device__ float g_V  [MTOT * EDIM];
__device__ float g_QA [(size_t)MTOT * QASTR];   // [SO(256) | AWL(128)]
__device__ __nv_bfloat16 g_Aval[(size_t)MTOT * KP2];
__device__ __nv_bfloat16 g_Aq  [(size_t)MTOT * KP2];
__device__ __nv_bfloat16 g_Atmp[(size_t)MTOT * KP2];
__device__ __nv_bfloat16 g_Bv [256 * KP2];
__device__ __nv_bfloat16 g_Bqa[QASTR * KP2];
__device__ __nv_bfloat16 g_Bo [256 * KP2];
__device__ float g_biasQA[QASTR];

// -------------------------- small PTX helpers -------------------------------
__device__ __forceinline__ uint32_t smem_u32(const void* p) {
    uint32_t a;
    asm("{ .reg .u64 t; cvta.to.shared.u64 t, %1; cvt.u32.u64 %0, t; }"
        : "=r"(a) : "l"(p));
    return a;
}
__device__ __forceinline__ void cp_async16(uint32_t dst, const void* src) {
    asm volatile("cp.async.cg.shared.global [%0], [%1], 16;"
                 :: "r"(dst), "l"(src) : "memory");
}
__device__ __forceinline__ void cp_commit() {
    asm volatile("cp.async.commit_group;" ::: "memory");
}
template <int N>
__device__ __forceinline__ void cp_wait() {
    asm volatile("cp.async.wait_group %0;" :: "n"(N) : "memory");
}
__device__ __forceinline__ void ldmatrix_x4(uint32_t* r, uint32_t addr) {
    asm volatile("ldmatrix.sync.aligned.m8n8.x4.shared.b16 {%0,%1,%2,%3}, [%4];"
                 : "=r"(r[0]), "=r"(r[1]), "=r"(r[2]), "=r"(r[3]) : "r"(addr));
}
__device__ __forceinline__ void mma_bf16(float* c, const uint32_t* a,
                                         uint32_t b0, uint32_t b1) {
    asm volatile(
        "mma.sync.aligned.m16n8k16.row.col.f32.bf16.bf16.f32 "
        "{%0,%1,%2,%3}, {%4,%5,%6,%7}, {%8,%9}, {%0,%1,%2,%3};"
        : "+f"(c[0]), "+f"(c[1]), "+f"(c[2]), "+f"(c[3])
        : "r"(a[0]), "r"(a[1]), "r"(a[2]), "r"(a[3]), "r"(b0), "r"(b1));
}

// ---------------------------------------------------------------------------
// fp32 activation -> bf16 [hi(256) | lo(256)], row stride KP2
// ---------------------------------------------------------------------------
__global__ __launch_bounds__(256) void split_cat(
    const float* __restrict__ x, __nv_bfloat16* __restrict__ out, int n4)
{
    const int i = blockIdx.x * 256 + threadIdx.x;
    if (i >= n4) return;
    const float4 v = ((const float4*)x)[i];
    const int row = i >> 6;
    const int c4  = (i & 63) << 2;
    __nv_bfloat16 h[4], l[4];
    const float f[4] = {v.x, v.y, v.z, v.w};
#pragma unroll
    for (int k = 0; k < 4; k++) {
        h[k] = __float2bfloat16(f[k]);
        l[k] = __float2bfloat16(f[k] - __bfloat162float(h[k]));
    }
    __nv_bfloat16* base = out + (size_t)row * KP2 + c4;
    *(uint2*)(base)       = *(const uint2*)h;
    *(uint2*)(base + 256) = *(const uint2*)l;
}

// ---------------------------------------------------------------------------
// One-shot weight prep: W[K=256,N] -> B't[N][KP2]=[h|l] transposed + bias cat.
// ---------------------------------------------------------------------------
__global__ __launch_bounds__(256) void prep_weights(
    const float* __restrict__ Wv,  const float* __restrict__ Wso,
    const float* __restrict__ Waw, const float* __restrict__ Wo,
    const float* __restrict__ bso, const float* __restrict__ baw)
{
    const int idx = blockIdx.x * 256 + threadIdx.x;
    const float* W;
    __nv_bfloat16* Bt;
    int li, N, nofs = 0;
    if (idx < 65536)        { W = Wv;  Bt = g_Bv;  li = idx;          N = 256; }
    else if (idx < 131072)  { W = Wso; Bt = g_Bqa; li = idx - 65536;  N = 256; }
    else if (idx < 163840)  { W = Waw; Bt = g_Bqa; li = idx - 131072; N = 128; nofs = 256; }
    else if (idx < 229376)  { W = Wo;  Bt = g_Bo;  li = idx - 163840; N = 256; }
    else {
        const int i = idx - 229376;
        if (i < 256)      g_biasQA[i] = bso[i];
        else if (i < 384) g_biasQA[i] = baw[i - 256];
        return;
    }
    const int k = li / N, n = li % N;
    const float v = W[li];
    const __nv_bfloat16 h = __float2bfloat16(v);
    const __nv_bfloat16 l = __float2bfloat16(v - __bfloat162float(h));
    __nv_bfloat16* base = Bt + (size_t)(n + nofs) * KP2 + k;
    base[0]   = h;
    base[256] = l;
}

// ---------------------------------------------------------------------------
// bf16 mma GEMM with register-reuse 3-term compensation (round-6, unchanged).
// ---------------------------------------------------------------------------
__global__ __launch_bounds__(256, 2) void gemm_mma(
    const __nv_bfloat16* __restrict__ A, const __nv_bfloat16* __restrict__ Bt,
    const float* __restrict__ bias, const float* __restrict__ res,
    float* __restrict__ C, int M, int N)
{
    extern __shared__ __align__(16) char smem[];
    const uint32_t sBase = smem_u32(smem);

    const int tid  = threadIdx.x;
    const int lane = tid & 31;
    const int wid  = tid >> 5;
    const int wm   = wid & 3;
    const int wn   = wid >> 2;
    const int m0   = blockIdx.x * 128;
    const int n0   = blockIdx.y * 128;

    auto load_stage = [&](int stg, int kt) {
        const int kbase = kt * BK;
        const uint32_t sA = sBase + (uint32_t)stg * STAGE_B;
        const uint32_t sB = sA + TILE_E * 2;
#pragma unroll
        for (int it = 0; it < 4; it++) {
            const int c   = tid + it * 256;
            const int row = c >> 3;
            const int seg = (c & 7) << 3;
            const int gcol = (seg < 32) ? (kbase + seg) : (256 + kbase + seg - 32);
            const uint32_t soff = (uint32_t)(row * APAD2 + seg) * 2;
            const int ar = min(m0 + row, M - 1);
            cp_async16(sA + soff, A + (size_t)ar * KP2 + gcol);
            cp_async16(sB + soff, Bt + (size_t)(n0 + row) * KP2 + gcol);
        }
    };

    float acc[2][8][4];
#pragma unroll
    for (int mi = 0; mi < 2; mi++)
#pragma unroll
        for (int nj = 0; nj < 8; nj++)
#pragma unroll
            for (int k = 0; k < 4; k++) acc[mi][nj][k] = 0.f;

    load_stage(0, 0); cp_commit();
    load_stage(1, 1); cp_commit();

    int stg = 0;
#pragma unroll 1
    for (int kt = 0; kt < NKIT; kt++) {
        cp_wait<1>();
        __syncthreads();

        if (kt + 2 < NKIT) load_stage((stg + 2) % 3, kt + 2);
        cp_commit();

        const uint32_t aB = sBase + (uint32_t)stg * STAGE_B;
        const uint32_t bB = aB + TILE_E * 2;

#pragma unroll
        for (int ks = 0; ks < 2; ks++) {
            uint32_t ah[2][4], al[2][4];
#pragma unroll
            for (int mi = 0; mi < 2; mi++) {
                const int row = wm * 32 + mi * 16 + (lane & 15);
                const int col = ks * 16 + ((lane >> 4) << 3);
                ldmatrix_x4(ah[mi], aB + (uint32_t)(row * APAD2 + col) * 2);
                ldmatrix_x4(al[mi], aB + (uint32_t)(row * APAD2 + 32 + col) * 2);
            }
#pragma unroll
            for (int njp = 0; njp < 4; njp++) {
                const int row = wn * 64 + njp * 16 + ((lane >> 4) & 1) * 8 + (lane & 7);
                const int col = ks * 16 + ((lane >> 3) & 1) * 8;
                uint32_t bh[4], bl[4];
                ldmatrix_x4(bh, bB + (uint32_t)(row * APAD2 + col) * 2);
                ldmatrix_x4(bl, bB + (uint32_t)(row * APAD2 + 32 + col) * 2);
#pragma unroll
                for (int mi = 0; mi < 2; mi++) {
                    float* a0 = acc[mi][njp * 2];
                    float* a1 = acc[mi][njp * 2 + 1];
                    mma_bf16(a0, ah[mi], bh[0], bh[1]);
                    mma_bf16(a1, ah[mi], bh[2], bh[3]);
                    mma_bf16(a0, ah[mi], bl[0], bl[1]);
                    mma_bf16(a1, ah[mi], bl[2], bl[3]);
                    mma_bf16(a0, al[mi], bh[0], bh[1]);
                    mma_bf16(a1, al[mi], bh[2], bh[3]);
                }
            }
        }
        stg = (stg + 1) % 3;
    }

#pragma unroll
    for (int mi = 0; mi < 2; mi++) {
#pragma unroll
        for (int nj = 0; nj < 8; nj++) {
            const int col = n0 + wn * 64 + nj * 8 + (lane & 3) * 2;
            const int r0  = m0 + wm * 32 + mi * 16 + (lane >> 2);
            const int r1  = r0 + 8;
            const float b0 = bias[col], b1 = bias[col + 1];
            if (r0 < M) {
                float2 o = make_float2(acc[mi][nj][0] + b0, acc[mi][nj][1] + b1);
                if (res) {
                    const float2 rv = *(const float2*)(res + (size_t)r0 * N + col);
                    o.x += rv.x; o.y += rv.y;
                }
                *(float2*)(C + (size_t)r0 * N + col) = o;
            }
            if (r1 < M) {
                float2 o = make_float2(acc[mi][nj][2] + b0, acc[mi][nj][3] + b1);
                if (res) {
                    const float2 rv = *(const float2*)(res + (size_t)r1 * N + col);
                    o.x += rv.x; o.y += rv.y;
                }
                *(float2*)(C + (size_t)r1 * N + col) = o;
            }
        }
    }
}

// ---------------------------------------------------------------------------
// Sampler v4: block = 2 queries (256 threads), warp = (query, head-pair).
// Phase A: exactly 1 thread per (q,h,pt): softmax in width-16 shuffle groups,
//   pre-scaled byte offsets + aw-folded weights -> smem.
// Phase B: warp w -> q = w>>2, heads {2j, 2j+1} (j = w&3); half-warp = head,
//   lane-in-half = channel pair (float2). Each LDG.64 touches exactly 2
//   aligned 128B lines (one per half-warp): cost ~3.07 cyc/LDG, issue 127k/SM.
// ---------------------------------------------------------------------------
__global__ __launch_bounds__(256) void msda_sample_p2(
    const float* __restrict__ V, const float* __restrict__ QA,
    const float* __restrict__ refp,
    const int* __restrict__ shapes, const int* __restrict__ starts,
    __nv_bfloat16* __restrict__ outCat, int M)
{
    __shared__ int4   sOff[2][16][8];   // [q][pt][h]: 4 corner byte-offsets
    __shared__ float4 sW  [2][16][8];   // [q][pt][h]: 4 corner weights * aw

    const int tid = threadIdx.x;

    // -------------------- Phase A: 1 thread per (q,h,pt) -------------------
    {
        const int q  = tid >> 7;         // 0/1
        const int h  = (tid >> 4) & 7;
        const int pt = tid & 15;
        int bq = blockIdx.x * 2 + q;
        bq = min(bq, M - 1);

        const float logit = QA[(size_t)bq * QASTR + 256 + h * 16 + pt];
        float mx = logit;
#pragma unroll
        for (int off = 8; off; off >>= 1)
            mx = fmaxf(mx, __shfl_xor_sync(0xffffffffu, mx, off, 16));
        const float e = expf(logit - mx);
        float sm = e;
#pragma unroll
        for (int off = 8; off; off >>= 1)
            sm += __shfl_xor_sync(0xffffffffu, sm, off, 16);
        const float aw = e / sm;

        const int l  = pt >> 2;
        const int H  = shapes[2 * l + 0];
        const int W  = shapes[2 * l + 1];
        const int st = starts[l];
        const float2 rp = *(const float2*)(refp + ((size_t)bq * NLVL + l) * 2);
        const float2 so = *(const float2*)(QA + (size_t)bq * QASTR + h * 32 + pt * 2);

        const float x = fmaf(rp.x, (float)W, so.x) - 0.5f;
        const float y = fmaf(rp.y, (float)H, so.y) - 0.5f;
        const float xf = floorf(x), yf = floorf(y);
        const int x0 = (int)xf, y0 = (int)yf;
        const float wx1 = x - xf, wx0 = 1.f - wx1;
        const float wy1 = y - yf, wy0 = 1.f - wy1;

        const bool vx0 = (x0 >= 0) && (x0 < W);
        const bool vx1 = (x0 + 1 >= 0) && (x0 + 1 < W);
        const bool vy0 = (y0 >= 0) && (y0 < H);
        const bool vy1 = (y0 + 1 >= 0) && (y0 + 1 < H);

        const int cx0 = max(0, min(x0,     W - 1));
        const int cx1 = max(0, min(x0 + 1, W - 1));
        const int cy0 = max(0, min(y0,     H - 1));
        const int cy1 = max(0, min(y0 + 1, H - 1));

        int4 o;   // byte offsets (value-row stride = EDIM*4 = 1024B)
        o.x = (st + cy0 * W + cx0) << 10;
        o.y = (st + cy0 * W + cx1) << 10;
        o.z = (st + cy1 * W + cx0) << 10;
        o.w = (st + cy1 * W + cx1) << 10;

        float4 w4;
        w4.x = (vx0 && vy0) ? wx0 * wy0 * aw : 0.f;
        w4.y = (vx1 && vy0) ? wx1 * wy0 * aw : 0.f;
        w4.z = (vx0 && vy1) ? wx0 * wy1 * aw : 0.f;
        w4.w = (vx1 && vy1) ? wx1 * wy1 * aw : 0.f;

        sOff[q][pt][h] = o;
        sW  [q][pt][h] = w4;
    }
    __syncthreads();

    // -------------------- Phase B ------------------------------------------
    const int wid  = tid >> 5;
    const int lane = tid & 31;
    const int q    = wid >> 2;                    // 0/1
    const int h    = ((wid & 3) << 1) + (lane >> 4);  // head 0..7
    const int chp  = lane & 15;                   // channel pair (float2)
    const int bq   = blockIdx.x * 2 + q;
    if (bq >= M) return;
    const int b = bq / NQ;

    const char* vb = (const char*)(V + (size_t)b * NQ * EDIM + h * 32 + chp * 2);

    float2 acc = make_float2(0.f, 0.f);
#pragma unroll
    for (int pt = 0; pt < 16; pt++) {
        const int4   o = sOff[q][pt][h];
        const float4 w = sW [q][pt][h];
        const float2 v0 = *(const float2*)(vb + o.x);
        const float2 v1 = *(const float2*)(vb + o.y);
        const float2 v2 = *(const float2*)(vb + o.z);
        const float2 v3 = *(const float2*)(vb + o.w);
        acc.x = fmaf(w.x, v0.x, acc.x); acc.y = fmaf(w.x, v0.y, acc.y);
        acc.x = fmaf(w.y, v1.x, acc.x); acc.y = fmaf(w.y, v1.y, acc.y);
        acc.x = fmaf(w.z, v2.x, acc.x); acc.y = fmaf(w.z, v2.y, acc.y);
        acc.x = fmaf(w.w, v3.x, acc.x); acc.y = fmaf(w.w, v3.y, acc.y);
    }

    // emit [hi|lo] bf16 pair for the output GEMM
    __nv_bfloat16 hh[2], ll[2];
    const float f[2] = {acc.x, acc.y};
#pragma unroll
    for (int k = 0; k < 2; k++) {
        hh[k] = __float2bfloat16(f[k]);
        ll[k] = __float2bfloat16(f[k] - __bfloat162float(hh[k]));
    }
    __nv_bfloat16* base = outCat + (size_t)bq * KP2 + h * 32 + chp * 2;
    *(uint32_t*)(base)       = *(const uint32_t*)hh;
    *(uint32_t*)(base + 256) = *(const uint32_t*)ll;
}

// ---------------------------------------------------------------------------
// Launch
// ---------------------------------------------------------------------------
extern "C" void kernel_launch(void* const* d_in, const int* in_sizes, int n_in,
                              void* d_out, int out_size)
{
    const float* query  = (const float*)d_in[0];
    const float* value  = (const float*)d_in[1];
    const float* refp   = (const float*)d_in[2];
    const int*   shapes = (const int*)  d_in[3];
    const int*   starts = (const int*)  d_in[4];
    const float* Wv  = (const float*)d_in[5];
    const float* bv  = (const float*)d_in[6];
    const float* Wso = (const float*)d_in[7];
    const float* bso = (const float*)d_in[8];
    const float* Waw = (const float*)d_in[9];
    const float* baw = (const float*)d_in[10];
    const float* Wo  = (const float*)d_in[11];
    const float* bo  = (const float*)d_in[12];
    float* out = (float*)d_out;

    const int M = in_sizes[0] / EDIM;   // 40394

    float *pV, *pQA, *pBiasQA;
    __nv_bfloat16 *pAval, *pAq, *pAtmp, *pBv, *pBqa, *pBo;
    cudaGetSymbolAddress((void**)&pV,     g_V);
    cudaGetSymbolAddress((void**)&pQA,    g_QA);
    cudaGetSymbolAddress((void**)&pBiasQA,g_biasQA);
    cudaGetSymbolAddress((void**)&pAval,  g_Aval);
    cudaGetSymbolAddress((void**)&pAq,    g_Aq);
    cudaGetSymbolAddress((void**)&pAtmp,  g_Atmp);
    cudaGetSymbolAddress((void**)&pBv,    g_Bv);
    cudaGetSymbolAddress((void**)&pBqa,   g_Bqa);
    cudaGetSymbolAddress((void**)&pBo,    g_Bo);

    cudaFuncSetAttribute(gemm_mma, cudaFuncAttributeMaxDynamicSharedMemorySize, SMEM_GEMM);

    const int n4 = M * (EDIM / 4);
    const int cvtBlocks = (n4 + 255) / 256;
    const int mTiles = (M + 127) / 128;
    const dim3 g256(mTiles, 2);
    const dim3 g384(mTiles, 3);

    split_cat<<<cvtBlocks, 256>>>(value, pAval, n4);
    split_cat<<<cvtBlocks, 256>>>(query, pAq,   n4);
    prep_weights<<<(229760 + 255) / 256, 256>>>(Wv, Wso, Waw, Wo, bso, baw);

    gemm_mma<<<g256, 256, SMEM_GEMM>>>(pAval, pBv,  bv,      nullptr, pV,  M, 256);
    gemm_mma<<<g384, 256, SMEM_GEMM>>>(pAq,   pBqa, pBiasQA, nullptr, pQA, M, QASTR);
    msda_sample_p2<<<(M + 1) / 2, 256>>>(pV, pQA, refp, shapes, starts, pAtmp, M);
    gemm_mma<<<g256, 256, SMEM_GEMM>>>(pAtmp, pBo,  bo,      query,   out, M, 256);
}